// round 16
// baseline (speedup 1.0000x reference)
#include <cuda_runtime.h>
#include <math.h>

#define BB 4
#define LL 2048
#define VV 32000
#define BL (BB * LL)

// Scratch (allocation-free rule: __device__ globals)
__device__ float4 g_sE[BL];   // gathered token embeddings, .w unused
__device__ float2 g_r[LL];    // r_m = beta_attn * (Mp @ Ppos[m])
__device__ float4 g_g[BL];    // g[b,l] = beta_class * (c_E @ W3), .w unused

__device__ __forceinline__ float softplus_f(float x) {
    return (x > 20.f) ? x : log1pf(expf(x));
}

// ---------------------------------------------------------------------------
// Kernel 0: gather embeddings per token; precompute score vectors r_m.
// R13 proved this kernel earns its ~5.5us: staging E into g_sE saves ~40us
// of scattered re-gathers inside attn. R7/R10 validated shape.
// ---------------------------------------------------------------------------
#define PREP_TPB 64
__global__ void __launch_bounds__(PREP_TPB) prep_kernel(
    const int* __restrict__ x,
    const float* __restrict__ E,
    const float* __restrict__ P,
    const float* __restrict__ M,
    const float* __restrict__ raw_beta_attn) {
    int idx = blockIdx.x * PREP_TPB + threadIdx.x;
    if (idx >= BL) return;
    int tok = __ldg(&x[idx]);
    float4 v;
    v.x = __ldg(&E[3 * tok + 0]);
    v.y = __ldg(&E[3 * tok + 1]);
    v.z = __ldg(&E[3 * tok + 2]);
    v.w = 0.f;
    g_sE[idx] = v;

    if (idx < LL) {
        float beta = softplus_f(raw_beta_attn[0]) + 1e-6f;
        float p0 = P[2 * idx + 0];
        float p1 = P[2 * idx + 1];
        // Mp = M[3:,3:] of row-major 5x5 -> indices 18,19,23,24
        float2 r;
        r.x = beta * (M[18] * p0 + M[19] * p1);
        r.y = beta * (M[23] * p0 + M[24] * p1);
        g_r[idx] = r;
    }
}

// ---------------------------------------------------------------------------
// Kernel 1: ONE BLOCK PER ROW l (validated: warp-per-row +16us in R8,
// fused direct-gather +40us in R13). score[l,m] = q_l . r_m.
// Single-pass softmax: |score| ~ 0.05 -> no overflow; shift-invariant.
// ---------------------------------------------------------------------------
__global__ void attn_kernel(const float* __restrict__ P,
                            const float* __restrict__ W,
                            const float* __restrict__ raw_beta_class) {
    const int l = blockIdx.x;
    const int tid = threadIdx.x;

    if (l == 0) {
        // fully-masked row -> alpha = 0 -> g = 0
        if (tid < BB) g_g[tid * LL] = make_float4(0.f, 0.f, 0.f, 0.f);
        return;
    }

    const float q0 = P[2 * l + 0];
    const float q1 = P[2 * l + 1];

    // ---- single pass: exp-sum + weighted embedding sums (4 batches x 3) ----
    float sum = 0.f;
    float acc[BB][3];
    #pragma unroll
    for (int b = 0; b < BB; b++) {
        acc[b][0] = 0.f; acc[b][1] = 0.f; acc[b][2] = 0.f;
    }
    for (int m = tid; m < l; m += blockDim.x) {
        float2 r = g_r[m];
        float e = __expf(fmaf(q0, r.x, q1 * r.y));
        sum += e;
        #pragma unroll
        for (int b = 0; b < BB; b++) {
            float4 s = g_sE[b * LL + m];
            acc[b][0] = fmaf(e, s.x, acc[b][0]);
            acc[b][1] = fmaf(e, s.y, acc[b][1]);
            acc[b][2] = fmaf(e, s.z, acc[b][2]);
        }
    }

    // ---- reduce 13 floats: warp shuffle then cross-warp via smem ----
    int warp = tid >> 5, lane = tid & 31;
    #pragma unroll
    for (int o = 16; o > 0; o >>= 1) {
        sum += __shfl_xor_sync(0xffffffffu, sum, o);
        #pragma unroll
        for (int b = 0; b < BB; b++) {
            acc[b][0] += __shfl_xor_sync(0xffffffffu, acc[b][0], o);
            acc[b][1] += __shfl_xor_sync(0xffffffffu, acc[b][1], o);
            acc[b][2] += __shfl_xor_sync(0xffffffffu, acc[b][2], o);
        }
    }
    __shared__ float wred[8][13];
    if (lane == 0) {
        wred[warp][0] = sum;
        #pragma unroll
        for (int b = 0; b < BB; b++) {
            wred[warp][1 + 3 * b + 0] = acc[b][0];
            wred[warp][1 + 3 * b + 1] = acc[b][1];
            wred[warp][1 + 3 * b + 2] = acc[b][2];
        }
    }
    __syncthreads();

    if (tid == 0) {
        float tot = 0.f;
        float a[BB][3];
        #pragma unroll
        for (int b = 0; b < BB; b++) { a[b][0] = 0.f; a[b][1] = 0.f; a[b][2] = 0.f; }
        #pragma unroll
        for (int w = 0; w < 8; w++) {
            tot += wred[w][0];
            #pragma unroll
            for (int b = 0; b < BB; b++) {
                a[b][0] += wred[w][1 + 3 * b + 0];
                a[b][1] += wred[w][1 + 3 * b + 1];
                a[b][2] += wred[w][1 + 3 * b + 2];
            }
        }
        float inv = 1.f / tot;
        float bc = softplus_f(raw_beta_class[0]) + 1e-6f;
        #pragma unroll
        for (int b = 0; b < BB; b++) {
            float c0 = a[b][0] * inv;
            float c1 = a[b][1] * inv;
            float c2 = a[b][2] * inv;
            // h[d] = sum_k c[k] * W[k*5+d], d<3 ; fold beta_class
            float4 g;
            g.x = bc * (c0 * W[0] + c1 * W[5] + c2 * W[10]);
            g.y = bc * (c0 * W[1] + c1 * W[6] + c2 * W[11]);
            g.z = bc * (c0 * W[2] + c1 * W[7] + c2 * W[12]);
            g.w = 0.f;
            g_g[b * LL + l] = g;
        }
    }
}

// ---------------------------------------------------------------------------
// Kernel 2: logits[b,l,v] = g[b,l] . E[v]   (1.05 GB streaming-store bound)
// R13 profile: 147.5us, DRAM=84.6%, occ=66.3% (regs=38, 256thr -> 6 CTAs/SM,
// 48 warps). OCCUPANCY FIX WITHOUT launch_bounds minBlocks (that attribute
// correlates with 2x container failures): 128-thread CTAs at same ~38 regs
// -> ~13 CTAs/SM -> 52 warps (81%) and finer-grain scheduling. More blocks
// also matched the R9 lesson (more blocks > fewer on this kernel).
// ---------------------------------------------------------------------------
#define OUT_TPB 128
#define OUT_VPT 4
#define OUT_VCHUNK (OUT_TPB * OUT_VPT)   // 512 v per block-x
#define OUT_BLPB 64                      // (b,l) rows per block-y

__global__ void __launch_bounds__(OUT_TPB) out_kernel(
    const float* __restrict__ E, float* __restrict__ out) {
    __shared__ float4 sg[OUT_BLPB];

    const int bl0 = blockIdx.y * OUT_BLPB;
    if (threadIdx.x < OUT_BLPB)
        sg[threadIdx.x] = g_g[bl0 + threadIdx.x];

    const int v0 = blockIdx.x * OUT_VCHUNK + threadIdx.x * OUT_VPT;
    const bool act = (v0 < VV);

    float e0x=0,e0y=0,e0z=0, e1x=0,e1y=0,e1z=0, e2x=0,e2y=0,e2z=0, e3x=0,e3y=0,e3z=0;
    if (act) {
        // 12 floats at E + 3*v0, 16B-aligned since v0 % 4 == 0
        const float4* Ep = reinterpret_cast<const float4*>(E + 3 * v0);
        float4 a = Ep[0], b4 = Ep[1], c4 = Ep[2];
        e0x=a.x;  e0y=a.y;  e0z=a.z;
        e1x=a.w;  e1y=b4.x; e1z=b4.y;
        e2x=b4.z; e2y=b4.w; e2z=c4.x;
        e3x=c4.y; e3y=c4.z; e3z=c4.w;
    }
    __syncthreads();

    float* op = out + (size_t)bl0 * VV + v0;
    #pragma unroll 8
    for (int i = 0; i < OUT_BLPB; i++) {
        float4 g = sg[i];               // LDS broadcast, conflict-free
        if (act) {
            float4 o;
            o.x = fmaf(g.x, e0x, fmaf(g.y, e0y, g.z * e0z));
            o.y = fmaf(g.x, e1x, fmaf(g.y, e1y, g.z * e1z));
            o.z = fmaf(g.x, e2x, fmaf(g.y, e2y, g.z * e2z));
            o.w = fmaf(g.x, e3x, fmaf(g.y, e3y, g.z * e3z));
            // streaming store: output is never re-read -> don't pollute L2
            __stcs(reinterpret_cast<float4*>(op), o);
        }
        op += VV;
    }
}

// ---------------------------------------------------------------------------
// Launch (R10-validated three-kernel layout, plain launches)
// ---------------------------------------------------------------------------
extern "C" void kernel_launch(void* const* d_in, const int* in_sizes, int n_in,
                              void* d_out, int out_size) {
    const int*   x   = (const int*)  d_in[0];  // [B, L]
    const float* E   = (const float*)d_in[1];  // [V, 3]
    const float* P   = (const float*)d_in[2];  // [L, 2]
    const float* M   = (const float*)d_in[3];  // [5, 5]
    const float* W   = (const float*)d_in[4];  // [5, 5]
    const float* rba = (const float*)d_in[5];  // scalar
    const float* rbc = (const float*)d_in[6];  // scalar
    float* out = (float*)d_out;                // [B, L, V]

    prep_kernel<<<(BL + PREP_TPB - 1) / PREP_TPB, PREP_TPB>>>(x, E, P, M, rba);
    attn_kernel<<<LL, 256>>>(P, W, rbc);

    dim3 grid((VV + OUT_VCHUNK - 1) / OUT_VCHUNK, BL / OUT_BLPB);
    out_kernel<<<grid, OUT_TPB>>>(E, out);
}

// round 17
// speedup vs baseline: 1.3739x; 1.3739x over previous
#include <cuda_runtime.h>
#include <math.h>

#define BB 4
#define LL 2048
#define VV 32000
#define BL (BB * LL)

// Scratch (allocation-free rule: __device__ globals)
__device__ float4 g_sE[BL];   // gathered token embeddings, .w unused
__device__ float4 g_g[BL];    // g[b,l] = beta_class * (c_E @ W3), .w unused

__device__ __forceinline__ float softplus_f(float x) {
    return (x > 20.f) ? x : log1pf(expf(x));
}

// ---------------------------------------------------------------------------
// Kernel 0: gather embeddings per token into g_sE (stage once, stream many:
// R13 proved deleting this costs ~40us of scattered re-gathers in attn).
// R7/R10 validated shape (~5.5us cold-touch/launch floor).
// ---------------------------------------------------------------------------
#define PREP_TPB 64
__global__ void __launch_bounds__(PREP_TPB) prep_kernel(
    const int* __restrict__ x,
    const float* __restrict__ E) {
    int idx = blockIdx.x * PREP_TPB + threadIdx.x;
    if (idx >= BL) return;
    int tok = __ldg(&x[idx]);
    float4 v;
    v.x = __ldg(&E[3 * tok + 0]);
    v.y = __ldg(&E[3 * tok + 1]);
    v.z = __ldg(&E[3 * tok + 2]);
    v.w = 0.f;
    g_sE[idx] = v;
}

// ---------------------------------------------------------------------------
// Kernel 1: ONE BLOCK PER ROW l (validated: warp-per-row +16us in R8,
// fused direct-gather +40us in R13).
// Score via row-fold: u = beta * Mp^T q_l, so score[l,m] = u . P[m]
// (2 FMAs/block extra; P[m] has identical size/pattern to the old g_r[m]).
// Single-pass softmax: |score| ~ 0.05 (M scaled 0.001) -> no overflow;
// softmax is shift-invariant so the max pass is redundant.
// ---------------------------------------------------------------------------
__global__ void attn_kernel(const float* __restrict__ P,
                            const float* __restrict__ M,
                            const float* __restrict__ W,
                            const float* __restrict__ raw_beta_attn,
                            const float* __restrict__ raw_beta_class) {
    const int l = blockIdx.x;
    const int tid = threadIdx.x;

    if (l == 0) {
        // fully-masked row -> alpha = 0 -> g = 0
        if (tid < BB) g_g[tid * LL] = make_float4(0.f, 0.f, 0.f, 0.f);
        return;
    }

    // u = beta * Mp^T q_l  (Mp = M[3:,3:] -> indices 18,19,23,24 row-major)
    const float q0 = P[2 * l + 0];
    const float q1 = P[2 * l + 1];
    const float beta = softplus_f(raw_beta_attn[0]) + 1e-6f;
    const float u0 = beta * fmaf(q0, M[18], q1 * M[23]);
    const float u1 = beta * fmaf(q0, M[19], q1 * M[24]);

    const float2* __restrict__ P2 = reinterpret_cast<const float2*>(P);

    // ---- single pass: exp-sum + weighted embedding sums (4 batches x 3) ----
    float sum = 0.f;
    float acc[BB][3];
    #pragma unroll
    for (int b = 0; b < BB; b++) {
        acc[b][0] = 0.f; acc[b][1] = 0.f; acc[b][2] = 0.f;
    }
    for (int m = tid; m < l; m += blockDim.x) {
        float2 pm = __ldg(&P2[m]);
        float e = __expf(fmaf(u0, pm.x, u1 * pm.y));
        sum += e;
        #pragma unroll
        for (int b = 0; b < BB; b++) {
            float4 s = g_sE[b * LL + m];
            acc[b][0] = fmaf(e, s.x, acc[b][0]);
            acc[b][1] = fmaf(e, s.y, acc[b][1]);
            acc[b][2] = fmaf(e, s.z, acc[b][2]);
        }
    }

    // ---- reduce 13 floats: warp shuffle then cross-warp via smem ----
    int warp = tid >> 5, lane = tid & 31;
    #pragma unroll
    for (int o = 16; o > 0; o >>= 1) {
        sum += __shfl_xor_sync(0xffffffffu, sum, o);
        #pragma unroll
        for (int b = 0; b < BB; b++) {
            acc[b][0] += __shfl_xor_sync(0xffffffffu, acc[b][0], o);
            acc[b][1] += __shfl_xor_sync(0xffffffffu, acc[b][1], o);
            acc[b][2] += __shfl_xor_sync(0xffffffffu, acc[b][2], o);
        }
    }
    __shared__ float wred[8][13];
    if (lane == 0) {
        wred[warp][0] = sum;
        #pragma unroll
        for (int b = 0; b < BB; b++) {
            wred[warp][1 + 3 * b + 0] = acc[b][0];
            wred[warp][1 + 3 * b + 1] = acc[b][1];
            wred[warp][1 + 3 * b + 2] = acc[b][2];
        }
    }
    __syncthreads();

    if (tid == 0) {
        float tot = 0.f;
        float a[BB][3];
        #pragma unroll
        for (int b = 0; b < BB; b++) { a[b][0] = 0.f; a[b][1] = 0.f; a[b][2] = 0.f; }
        #pragma unroll
        for (int w = 0; w < 8; w++) {
            tot += wred[w][0];
            #pragma unroll
            for (int b = 0; b < BB; b++) {
                a[b][0] += wred[w][1 + 3 * b + 0];
                a[b][1] += wred[w][1 + 3 * b + 1];
                a[b][2] += wred[w][1 + 3 * b + 2];
            }
        }
        float inv = 1.f / tot;
        float bc = softplus_f(raw_beta_class[0]) + 1e-6f;
        #pragma unroll
        for (int b = 0; b < BB; b++) {
            float c0 = a[b][0] * inv;
            float c1 = a[b][1] * inv;
            float c2 = a[b][2] * inv;
            // h[d] = sum_k c[k] * W[k*5+d], d<3 ; fold beta_class
            float4 g;
            g.x = bc * (c0 * W[0] + c1 * W[5] + c2 * W[10]);
            g.y = bc * (c0 * W[1] + c1 * W[6] + c2 * W[11]);
            g.z = bc * (c0 * W[2] + c1 * W[7] + c2 * W[12]);
            g.w = 0.f;
            g_g[b * LL + l] = g;
        }
    }
}

// ---------------------------------------------------------------------------
// Kernel 2: logits[b,l,v] = g[b,l] . E[v]   (1.05 GB streaming-store bound)
// EXACT R10-validated config (164.1us): TPB=256, VPT=4, BLPB=64, smem-staged
// g, __stcs float4 stores. Proven optimum: BLPB=128 (+9.5us, R9), TPB=128
// (+60us, R16), minBlocks=8 (container failures) all rejected. DRAM=84.6%
// busy here is the write-turnaround floor; do not perturb this grid shape.
// ---------------------------------------------------------------------------
#define OUT_TPB 256
#define OUT_VPT 4
#define OUT_VCHUNK (OUT_TPB * OUT_VPT)   // 1024 v per block-x
#define OUT_BLPB 64                      // (b,l) rows per block-y

__global__ void __launch_bounds__(OUT_TPB) out_kernel(
    const float* __restrict__ E, float* __restrict__ out) {
    __shared__ float4 sg[OUT_BLPB];

    const int bl0 = blockIdx.y * OUT_BLPB;
    if (threadIdx.x < OUT_BLPB)
        sg[threadIdx.x] = g_g[bl0 + threadIdx.x];

    const int v0 = blockIdx.x * OUT_VCHUNK + threadIdx.x * OUT_VPT;
    const bool act = (v0 < VV);

    float e0x=0,e0y=0,e0z=0, e1x=0,e1y=0,e1z=0, e2x=0,e2y=0,e2z=0, e3x=0,e3y=0,e3z=0;
    if (act) {
        // 12 floats at E + 3*v0, 16B-aligned since v0 % 4 == 0
        const float4* Ep = reinterpret_cast<const float4*>(E + 3 * v0);
        float4 a = Ep[0], b4 = Ep[1], c4 = Ep[2];
        e0x=a.x;  e0y=a.y;  e0z=a.z;
        e1x=a.w;  e1y=b4.x; e1z=b4.y;
        e2x=b4.z; e2y=b4.w; e2z=c4.x;
        e3x=c4.y; e3y=c4.z; e3z=c4.w;
    }
    __syncthreads();

    float* op = out + (size_t)bl0 * VV + v0;
    #pragma unroll 8
    for (int i = 0; i < OUT_BLPB; i++) {
        float4 g = sg[i];               // LDS broadcast, conflict-free
        if (act) {
            float4 o;
            o.x = fmaf(g.x, e0x, fmaf(g.y, e0y, g.z * e0z));
            o.y = fmaf(g.x, e1x, fmaf(g.y, e1y, g.z * e1z));
            o.z = fmaf(g.x, e2x, fmaf(g.y, e2y, g.z * e2z));
            o.w = fmaf(g.x, e3x, fmaf(g.y, e3y, g.z * e3z));
            // streaming store: output is never re-read -> don't pollute L2
            __stcs(reinterpret_cast<float4*>(op), o);
        }
        op += VV;
    }
}

// ---------------------------------------------------------------------------
// Launch (R10-validated three-kernel layout, plain launches)
// ---------------------------------------------------------------------------
extern "C" void kernel_launch(void* const* d_in, const int* in_sizes, int n_in,
                              void* d_out, int out_size) {
    const int*   x   = (const int*)  d_in[0];  // [B, L]
    const float* E   = (const float*)d_in[1];  // [V, 3]
    const float* P   = (const float*)d_in[2];  // [L, 2]
    const float* M   = (const float*)d_in[3];  // [5, 5]
    const float* W   = (const float*)d_in[4];  // [5, 5]
    const float* rba = (const float*)d_in[5];  // scalar
    const float* rbc = (const float*)d_in[6];  // scalar
    float* out = (float*)d_out;                // [B, L, V]

    prep_kernel<<<(BL + PREP_TPB - 1) / PREP_TPB, PREP_TPB>>>(x, E);
    attn_kernel<<<LL, 256>>>(P, M, W, rba, rbc);

    dim3 grid((VV + OUT_VCHUNK - 1) / OUT_VCHUNK, BL / OUT_BLPB);
    out_kernel<<<grid, OUT_TPB>>>(E, out);
}